// round 2
// baseline (speedup 1.0000x reference)
#include <cuda_runtime.h>
#include <math.h>

// Problem constants (B=4, H=16, S=1024, D=128, fp32)
#define Bn 4
#define Hn 16
#define Sn 1024
#define Dn 128
#define TQ 32            // query rows per CTA
#define TK 128           // k/v rows per smem chunk
#define NCHUNK (Sn / TK) // 8
#define KSTRIDE 132      // floats per smem tile row = 33 float4 (lane word-stride 132 mod 32 = 4 -> conflict-free LDS.128)
#define KSTRIDE4 33
#define SCALE 0.08838834764831845f // 1/sqrt(128)
#define NEG_BIG (-1.0e9f)

// Dynamic smem layout:
//   sc  : TQ x Sn            = 32768 floats (scores / probs)
//   kv  : TK x KSTRIDE       = 16896 floats (K or V chunk)
//   qs  : TQ x KSTRIDE       =  4224 floats
// total = 53888 floats = 215552 bytes (1 CTA/SM)
#define SMEM_FLOATS (TQ * Sn + TK * KSTRIDE + TQ * KSTRIDE)

extern __shared__ float smem_dyn[];

__global__ __launch_bounds__(256, 1)
void sdpa_fused_kernel(const float* __restrict__ Qg,
                       const float* __restrict__ Kg,
                       const float* __restrict__ Vg,
                       const int*   __restrict__ Mg,
                       float* __restrict__ ctx_out,
                       float* __restrict__ attn_out)
{
    const int qt  = blockIdx.x;           // query tile 0..31
    const int h   = blockIdx.y;
    const int b   = blockIdx.z;
    const int bh  = b * Hn + h;
    const int tid = threadIdx.x;
    const int ty  = tid >> 5;             // warp id 0..7 (q-row group)
    const int tx  = tid & 31;             // lane

    float* sc = smem_dyn;                       // [TQ][Sn]
    float* kv = sc + TQ * Sn;                   // [TK][KSTRIDE]
    float* qs = kv + TK * KSTRIDE;              // [TQ][KSTRIDE]

    const float* Qp = Qg + ((size_t)bh * Sn + (size_t)qt * TQ) * Dn;
    const float* Kp = Kg + (size_t)bh * Sn * Dn;
    const float* Vp = Vg + (size_t)bh * Sn * Dn;
    const int*   Mp = Mg + ((size_t)b * Sn + (size_t)qt * TQ) * Sn;

    // ---- load Q tile (32 rows x 32 float4) ----
    {
        const float4* Q4 = (const float4*)Qp;
        float4* q4 = (float4*)qs;
        #pragma unroll
        for (int it = 0; it < 4; ++it) {
            int idx = tid + 256 * it;          // 0..1023
            int row = idx >> 5, c4 = idx & 31;
            q4[row * KSTRIDE4 + c4] = Q4[row * 32 + c4];
        }
    }

    // ================= QK^T + mask =================
    for (int ck = 0; ck < NCHUNK; ++ck) {
        __syncthreads();  // protect kv from previous chunk's readers
        {
            const float4* K4 = (const float4*)(Kp + (size_t)ck * TK * Dn);
            float4* kv4 = (float4*)kv;
            #pragma unroll
            for (int it = 0; it < 16; ++it) {
                int idx = tid + 256 * it;      // 0..4095
                int row = idx >> 5, c4 = idx & 31;
                kv4[row * KSTRIDE4 + c4] = K4[row * 32 + c4];
            }
        }
        __syncthreads();

        float acc[4][4];
        #pragma unroll
        for (int i = 0; i < 4; ++i)
            #pragma unroll
            for (int j = 0; j < 4; ++j) acc[i][j] = 0.0f;

        const float4* q4 = (const float4*)qs;
        const float4* k4 = (const float4*)kv;

        #pragma unroll 4
        for (int d4 = 0; d4 < Dn / 4; ++d4) {
            float4 qv[4], kf[4];
            #pragma unroll
            for (int i = 0; i < 4; ++i) qv[i] = q4[(ty + 8 * i) * KSTRIDE4 + d4];   // broadcast
            #pragma unroll
            for (int j = 0; j < 4; ++j) kf[j] = k4[(tx + 32 * j) * KSTRIDE4 + d4];  // conflict-free
            #pragma unroll
            for (int i = 0; i < 4; ++i)
                #pragma unroll
                for (int j = 0; j < 4; ++j) {
                    acc[i][j] += qv[i].x * kf[j].x;
                    acc[i][j] += qv[i].y * kf[j].y;
                    acc[i][j] += qv[i].z * kf[j].z;
                    acc[i][j] += qv[i].w * kf[j].w;
                }
        }

        // scale + mask + store to score buffer
        #pragma unroll
        for (int i = 0; i < 4; ++i) {
            int qr = ty + 8 * i;
            #pragma unroll
            for (int j = 0; j < 4; ++j) {
                int kc = ck * TK + tx + 32 * j;
                int m = Mp[qr * Sn + kc];
                float s = (m == 0) ? NEG_BIG : acc[i][j] * SCALE;
                sc[qr * Sn + kc] = s;
            }
        }
    }
    __syncthreads();

    // ================= softmax (warp ty owns rows ty, ty+8, ty+16, ty+24) =================
    {
        float* attn_base = attn_out + ((size_t)bh * Sn + (size_t)qt * TQ) * Sn;
        #pragma unroll
        for (int i = 0; i < 4; ++i) {
            int row = ty + 8 * i;
            float* r = sc + row * Sn;
            float vals[32];
            float mx = -3.4e38f;
            #pragma unroll
            for (int m = 0; m < 32; ++m) {
                vals[m] = r[tx + 32 * m];
                mx = fmaxf(mx, vals[m]);
            }
            #pragma unroll
            for (int o = 16; o > 0; o >>= 1)
                mx = fmaxf(mx, __shfl_xor_sync(0xFFFFFFFFu, mx, o));
            float sum = 0.0f;
            #pragma unroll
            for (int m = 0; m < 32; ++m) {
                float p = __expf(vals[m] - mx);
                vals[m] = p;
                sum += p;
            }
            #pragma unroll
            for (int o = 16; o > 0; o >>= 1)
                sum += __shfl_xor_sync(0xFFFFFFFFu, sum, o);
            float inv = 1.0f / sum;
            float* ar = attn_base + (size_t)row * Sn;
            #pragma unroll
            for (int m = 0; m < 32; ++m) {
                float p = vals[m] * inv;
                r[tx + 32 * m] = p;   // keep normalized probs for PV
                ar[tx + 32 * m] = p;  // output attn
            }
        }
    }

    // ================= context = probs @ V =================
    float ca[4][4]; // [q-row group i][component of float4 at dv = tx*4 + c]
    #pragma unroll
    for (int i = 0; i < 4; ++i)
        #pragma unroll
        for (int j = 0; j < 4; ++j) ca[i][j] = 0.0f;

    for (int ck = 0; ck < NCHUNK; ++ck) {
        __syncthreads();  // protect kv from previous readers (QK phase or prior PV chunk)
        {
            const float4* V4 = (const float4*)(Vp + (size_t)ck * TK * Dn);
            float4* kv4 = (float4*)kv;
            #pragma unroll
            for (int it = 0; it < 16; ++it) {
                int idx = tid + 256 * it;
                int row = idx >> 5, c4 = idx & 31;
                kv4[row * KSTRIDE4 + c4] = V4[row * 32 + c4];
            }
        }
        __syncthreads();

        const float4* v4 = (const float4*)kv;
        // kc in pairs: 2x v loads (conflict-free) + 4x float2 prob broadcasts
        // -> LDS crossbar 96 cyc per 128 FMA-cyc SM-wide (FMA-bound with slack)
        #pragma unroll 2
        for (int kc = 0; kc < TK; kc += 2) {
            float4 vv0 = v4[(kc + 0) * KSTRIDE4 + tx];
            float4 vv1 = v4[(kc + 1) * KSTRIDE4 + tx];
            #pragma unroll
            for (int i = 0; i < 4; ++i) {
                // sc rows have even word stride (Sn=1024) and kc is even -> float2 aligned
                float2 p2 = *(const float2*)&sc[(ty + 8 * i) * Sn + ck * TK + kc]; // broadcast
                ca[i][0] += p2.x * vv0.x;
                ca[i][1] += p2.x * vv0.y;
                ca[i][2] += p2.x * vv0.z;
                ca[i][3] += p2.x * vv0.w;
                ca[i][0] += p2.y * vv1.x;
                ca[i][1] += p2.y * vv1.y;
                ca[i][2] += p2.y * vv1.z;
                ca[i][3] += p2.y * vv1.w;
            }
        }
    }

    // write context: row qr = ty+8i, cols [tx*4, tx*4+4)
    {
        float* ctx_base = ctx_out + ((size_t)bh * Sn + (size_t)qt * TQ) * Dn;
        #pragma unroll
        for (int i = 0; i < 4; ++i) {
            int qr = ty + 8 * i;
            float4 o = make_float4(ca[i][0], ca[i][1], ca[i][2], ca[i][3]);
            ((float4*)(ctx_base + (size_t)qr * Dn))[tx] = o;
        }
    }
}

extern "C" void kernel_launch(void* const* d_in, const int* in_sizes, int n_in,
                              void* d_out, int out_size) {
    const float* q    = (const float*)d_in[0];
    const float* k    = (const float*)d_in[1];
    const float* v    = (const float*)d_in[2];
    const int*   mask = (const int*)d_in[3];

    float* out = (float*)d_out;
    // Output order matches reference tuple: context [B,H,S,D] then attn [B,H,S,S]
    const size_t ctx_elems = (size_t)Bn * Hn * Sn * Dn;
    float* ctx_ptr  = out;
    float* attn_ptr = out + ctx_elems;

    const size_t smem_bytes = (size_t)SMEM_FLOATS * sizeof(float);
    cudaFuncSetAttribute(sdpa_fused_kernel,
                         cudaFuncAttributeMaxDynamicSharedMemorySize,
                         (int)smem_bytes);

    dim3 grid(Sn / TQ, Hn, Bn);   // (32, 16, 4)
    dim3 block(256);
    sdpa_fused_kernel<<<grid, block, smem_bytes>>>(q, k, v, mask, ctx_ptr, attn_ptr);
}

// round 5
// speedup vs baseline: 2.0984x; 2.0984x over previous
#include <cuda_runtime.h>
#include <cuda_bf16.h>
#include <cstdint>
#include <math.h>

// Problem constants (B=4, H=16, S=1024, D=128, fp32)
#define Bn 4
#define Hn 16
#define Sn 1024
#define Dn 128
#define BHn (Bn*Hn)
#define TQ 128
#define TN 128               // key chunk
#define NCHUNK (Sn/TN)       // 8
#define SCALEF 0.08838834764831845f
#define NELEM (Bn*Hn*Sn*Dn)  // 8388608

// Static split buffers + inv scratch (module-load allocation, allowed)
__device__ __align__(256) __nv_bfloat16 g_Qh[NELEM];
__device__ __align__(256) __nv_bfloat16 g_Ql[NELEM];
__device__ __align__(256) __nv_bfloat16 g_Kh[NELEM];
__device__ __align__(256) __nv_bfloat16 g_Kl[NELEM];
__device__ __align__(256) __nv_bfloat16 g_Vh[NELEM];   // natural [s][d] layout
__device__ __align__(256) __nv_bfloat16 g_Vl[NELEM];
__device__ float g_inv[BHn * Sn];

// ---------------- warp mma helpers ----------------
__device__ __forceinline__ uint32_t smem_u32(const void* p) {
    uint32_t a;
    asm("{ .reg .u64 t; cvta.to.shared.u64 t, %1; cvt.u32.u64 %0, t; }" : "=r"(a) : "l"(p));
    return a;
}

__device__ __forceinline__ void ldsm4(uint32_t r[4], uint32_t addr) {
    asm volatile("ldmatrix.sync.aligned.m8n8.x4.shared.b16 {%0,%1,%2,%3}, [%4];"
        : "=r"(r[0]), "=r"(r[1]), "=r"(r[2]), "=r"(r[3]) : "r"(addr));
}
__device__ __forceinline__ void ldsm4t(uint32_t r[4], uint32_t addr) {
    asm volatile("ldmatrix.sync.aligned.m8n8.x4.trans.shared.b16 {%0,%1,%2,%3}, [%4];"
        : "=r"(r[0]), "=r"(r[1]), "=r"(r[2]), "=r"(r[3]) : "r"(addr));
}
__device__ __forceinline__ void mma16816(float c[4], const uint32_t a[4], uint32_t b0, uint32_t b1) {
    asm volatile(
        "mma.sync.aligned.m16n8k16.row.col.f32.bf16.bf16.f32 "
        "{%0,%1,%2,%3}, {%4,%5,%6,%7}, {%8,%9}, {%0,%1,%2,%3};"
        : "+f"(c[0]), "+f"(c[1]), "+f"(c[2]), "+f"(c[3])
        : "r"(a[0]), "r"(a[1]), "r"(a[2]), "r"(a[3]), "r"(b0), "r"(b1));
}

// Swizzled smem address within a [128 x 128 bf16] tile: 256B rows, 16B chunk c16,
// chunk XOR (row&7) -> ldmatrix phases conflict-free
__device__ __forceinline__ uint32_t sw_addr(uint32_t tile, int row, int c16) {
    return tile + (row << 8) + (((c16 ^ (row & 7)) & 15) << 4);
}

// Copy a 128x128 bf16 tile (global, row stride 128 elems) into swizzled smem
__device__ __forceinline__ void copy_tile(uint32_t dst, const __nv_bfloat16* src, int tid) {
    #pragma unroll
    for (int it = 0; it < 8; ++it) {
        int idx = tid + 256 * it;              // 0..2047
        int row = idx >> 4, c16 = idx & 15;
        uint4 v = *(const uint4*)(src + (size_t)row * 128 + c16 * 8);
        asm volatile("st.shared.v4.b32 [%0], {%1,%2,%3,%4};"
            :: "r"(sw_addr(dst, row, c16)), "r"(v.x), "r"(v.y), "r"(v.z), "r"(v.w));
    }
}

// ---------------- smem ----------------
#define SM_QH 0
#define SM_QL 32768
#define SM_KH 65536          // K chunk, reused for V chunk
#define SM_KL 98304
#define SM_ROWSUM 131072     // 128 floats
#define SM_INV    131584     // 128 floats
#define SM_TOTAL  132096
#define CSTR 136             // ctx exchange row stride (floats), overlays smem base at end

extern __shared__ char sm_raw[];

__global__ __launch_bounds__(256, 1)
void sdpa_mma_kernel(const int* __restrict__ Mg,
                     float* __restrict__ ctx_out,
                     float* __restrict__ attn_out)
{
    const int qt = blockIdx.x;               // 0..7
    const int bh = blockIdx.y;               // 0..63
    const int b  = bh >> 4;
    const int tid  = threadIdx.x;
    const int wid  = tid >> 5;
    const int lane = tid & 31;
    const int wm = wid & 3;                  // m32 block
    const int wn = wid >> 2;                 // n64 / k64 block
    const int g  = lane >> 2;                // frag row group
    const int t  = lane & 3;                 // frag col pair
    const int lr = lane & 15, lc = lane >> 4;

    const uint32_t smb = smem_u32(sm_raw);
    float* rowsum_sm = (float*)(sm_raw + SM_ROWSUM);
    float* inv_sm    = (float*)(sm_raw + SM_INV);
    if (tid < 128) rowsum_sm[tid] = 0.0f;

    // Q tiles resident
    copy_tile(smb + SM_QH, g_Qh + ((size_t)bh * Sn + (size_t)qt * TQ) * Dn, tid);
    copy_tile(smb + SM_QL, g_Ql + ((size_t)bh * Sn + (size_t)qt * TQ) * Dn, tid);

    const __nv_bfloat16* Khp = g_Kh + (size_t)bh * Sn * Dn;
    const __nv_bfloat16* Klp = g_Kl + (size_t)bh * Sn * Dn;
    const __nv_bfloat16* Vhp = g_Vh + (size_t)bh * Sn * Dn;
    const __nv_bfloat16* Vlp = g_Vl + (size_t)bh * Sn * Dn;

    const int mbase = wm * 32;               // local q-row base for this warp
    float ctx[2][16][4];                     // [mtile][d n8-tile][frag]
    #pragma unroll
    for (int i = 0; i < 2; ++i)
        #pragma unroll
        for (int j = 0; j < 16; ++j)
            #pragma unroll
            for (int e = 0; e < 4; ++e) ctx[i][j][e] = 0.0f;
    float rs[2][2] = {{0.f, 0.f}, {0.f, 0.f}};  // rowsum acc [mtile][g / g+8]

    for (int ck = 0; ck < NCHUNK; ++ck) {
        __syncthreads();   // V tiles from prev chunk fully consumed
        copy_tile(smb + SM_KH, Khp + (size_t)ck * TN * Dn, tid);
        copy_tile(smb + SM_KL, Klp + (size_t)ck * TN * Dn, tid);
        __syncthreads();

        // ---- QK^T: acc[2 mtiles][8 n8-tiles][4] ----
        float qa[2][8][4];
        #pragma unroll
        for (int i = 0; i < 2; ++i)
            #pragma unroll
            for (int j = 0; j < 8; ++j)
                #pragma unroll
                for (int e = 0; e < 4; ++e) qa[i][j][e] = 0.0f;

        #pragma unroll
        for (int ks = 0; ks < 8; ++ks) {
            uint32_t aqh[2][4], aql[2][4];
            #pragma unroll
            for (int mt = 0; mt < 2; ++mt) {
                ldsm4(aqh[mt], sw_addr(smb + SM_QH, mbase + mt * 16 + lr, ks * 2 + lc));
                ldsm4(aql[mt], sw_addr(smb + SM_QL, mbase + mt * 16 + lr, ks * 2 + lc));
            }
            #pragma unroll
            for (int nt16 = 0; nt16 < 4; ++nt16) {
                int nb = wn * 64 + nt16 * 16;
                uint32_t bh4[4], bl4[4];
                ldsm4(bh4, sw_addr(smb + SM_KH, nb + lr, ks * 2 + lc));
                ldsm4(bl4, sw_addr(smb + SM_KL, nb + lr, ks * 2 + lc));
                #pragma unroll
                for (int mt = 0; mt < 2; ++mt) {
                    mma16816(qa[mt][nt16*2],   aqh[mt], bh4[0], bh4[2]);
                    mma16816(qa[mt][nt16*2],   aqh[mt], bl4[0], bl4[2]);
                    mma16816(qa[mt][nt16*2],   aql[mt], bh4[0], bh4[2]);
                    mma16816(qa[mt][nt16*2+1], aqh[mt], bh4[1], bh4[3]);
                    mma16816(qa[mt][nt16*2+1], aqh[mt], bl4[1], bl4[3]);
                    mma16816(qa[mt][nt16*2+1], aql[mt], bh4[1], bh4[3]);
                }
            }
        }

        // ---- epilogue: scale, mask, exp, rowsum, attn store, pack P frags ----
        uint32_t pah[4][2][4], pal[4][2][4];  // [kstep][mtile][a-frag]
        #pragma unroll
        for (int mt = 0; mt < 2; ++mt) {
            int r0 = qt * TQ + mbase + mt * 16 + g;        // global q rows
            const int*  mrow0 = Mg + ((size_t)(b * Sn + r0) << 10);
            const int*  mrow1 = mrow0 + (8 << 10);
            float* arow0 = attn_out + (((size_t)bh << 10) + r0) * Sn;
            float* arow1 = arow0 + ((size_t)8 * Sn);
            #pragma unroll
            for (int nt = 0; nt < 8; ++nt) {
                int col = ck * TN + wn * 64 + nt * 8 + 2 * t;
                int2 m0 = *(const int2*)(mrow0 + col);
                int2 m1 = *(const int2*)(mrow1 + col);
                float p0 = __expf(qa[mt][nt][0] * SCALEF) * (float)(m0.x != 0);
                float p1 = __expf(qa[mt][nt][1] * SCALEF) * (float)(m0.y != 0);
                float p2 = __expf(qa[mt][nt][2] * SCALEF) * (float)(m1.x != 0);
                float p3 = __expf(qa[mt][nt][3] * SCALEF) * (float)(m1.y != 0);
                rs[mt][0] += p0 + p1;
                rs[mt][1] += p2 + p3;
                *(float2*)(arow0 + col) = make_float2(p0, p1);
                *(float2*)(arow1 + col) = make_float2(p2, p3);
                // pack into PV A-frags (C layout == A layout)
                __nv_bfloat16 h0 = __float2bfloat16(p0), h1 = __float2bfloat16(p1);
                __nv_bfloat16 h2 = __float2bfloat16(p2), h3 = __float2bfloat16(p3);
                __nv_bfloat162 hv01 = __halves2bfloat162(h0, h1);
                __nv_bfloat162 hv23 = __halves2bfloat162(h2, h3);
                __nv_bfloat162 lv01 = __floats2bfloat162_rn(p0 - __bfloat162float(h0),
                                                            p1 - __bfloat162float(h1));
                __nv_bfloat162 lv23 = __floats2bfloat162_rn(p2 - __bfloat162float(h2),
                                                            p3 - __bfloat162float(h3));
                int ks = nt >> 1, hf = (nt & 1) * 2;
                pah[ks][mt][hf]     = *(uint32_t*)&hv01;
                pah[ks][mt][hf + 1] = *(uint32_t*)&hv23;
                pal[ks][mt][hf]     = *(uint32_t*)&lv01;
                pal[ks][mt][hf + 1] = *(uint32_t*)&lv23;
            }
        }

        __syncthreads();   // QK ldmatrix done everywhere -> safe to overwrite K tiles
        copy_tile(smb + SM_KH, Vhp + (size_t)ck * TN * Dn, tid);
        copy_tile(smb + SM_KL, Vlp + (size_t)ck * TN * Dn, tid);
        __syncthreads();

        // ---- PV: ctx += P[m32 x k64(wn half)] * V[k][d128] ----
        #pragma unroll
        for (int ks = 0; ks < 4; ++ks) {
            int kb = wn * 64 + ks * 16;
            #pragma unroll
            for (int dt = 0; dt < 8; ++dt) {
                uint32_t vh4[4], vl4[4];
                ldsm4t(vh4, sw_addr(smb + SM_KH, kb + lr, dt * 2 + lc));
                ldsm4t(vl4, sw_addr(smb + SM_KL, kb + lr, dt * 2 + lc));
                #pragma unroll
                for (int mt = 0; mt < 2; ++mt) {
                    mma16816(ctx[mt][dt*2],   pah[ks][mt], vh4[0], vh4[1]);
                    mma16816(ctx[mt][dt*2],   pah[ks][mt], vl4[0], vl4[1]);
                    mma16816(ctx[mt][dt*2],   pal[ks][mt], vh4[0], vh4[1]);
                    mma16816(ctx[mt][dt*2+1], pah[ks][mt], vh4[2], vh4[3]);
                    mma16816(ctx[mt][dt*2+1], pah[ks][mt], vl4[2], vl4[3]);
                    mma16816(ctx[mt][dt*2+1], pal[ks][mt], vh4[2], vh4[3]);
                }
            }
        }
    }

    // ---- rowsum finalize ----
    #pragma unroll
    for (int mt = 0; mt < 2; ++mt)
        #pragma unroll
        for (int hh = 0; hh < 2; ++hh) {
            rs[mt][hh] += __shfl_xor_sync(0xFFFFFFFFu, rs[mt][hh], 1);
            rs[mt][hh] += __shfl_xor_sync(0xFFFFFFFFu, rs[mt][hh], 2);
        }
    if (t == 0) {
        #pragma unroll
        for (int mt = 0; mt < 2; ++mt) {
            atomicAdd(&rowsum_sm[mbase + mt * 16 + g],     rs[mt][0]);
            atomicAdd(&rowsum_sm[mbase + mt * 16 + g + 8], rs[mt][1]);
        }
    }
    __syncthreads();
    if (tid < 128) {
        float iv = 1.0f / rowsum_sm[tid];
        inv_sm[tid] = iv;
        g_inv[((size_t)bh << 10) + qt * TQ + tid] = iv;
    }
    // ---- ctx exchange between k-half warps, normalize, write ----
    float* cbuf = (float*)sm_raw;    // overlays Q/K region: [4 pairs][32 rows][CSTR]
    float* mybuf = cbuf + wm * 32 * CSTR;
    __syncthreads();                 // inv ready AND smem tiles dead
    if (wn == 0) {
        #pragma unroll
        for (int mt = 0; mt < 2; ++mt)
            #pragma unroll
            for (int dt = 0; dt < 16; ++dt) {
                int rr = mt * 16 + g, dd = dt * 8 + 2 * t;
                *(float2*)(mybuf + rr * CSTR + dd)       = make_float2(ctx[mt][dt][0], ctx[mt][dt][1]);
                *(float2*)(mybuf + (rr + 8) * CSTR + dd) = make_float2(ctx[mt][dt][2], ctx[mt][dt][3]);
            }
    }
    __syncthreads();
    if (wn == 1) {
        #pragma unroll
        for (int mt = 0; mt < 2; ++mt) {
            int rl0 = mbase + mt * 16 + g;
            float iv0 = inv_sm[rl0], iv1 = inv_sm[rl0 + 8];
            float* crow0 = ctx_out + (((size_t)bh << 10) + qt * TQ + rl0) * Dn;
            float* crow1 = crow0 + (size_t)8 * Dn;
            #pragma unroll
            for (int dt = 0; dt < 16; ++dt) {
                int rr = mt * 16 + g, dd = dt * 8 + 2 * t;
                float2 o0 = *(float2*)(mybuf + rr * CSTR + dd);
                float2 o1 = *(float2*)(mybuf + (rr + 8) * CSTR + dd);
                *(float2*)(crow0 + dd) = make_float2((o0.x + ctx[mt][dt][0]) * iv0,
                                                     (o0.y + ctx[mt][dt][1]) * iv0);
                *(float2*)(crow1 + dd) = make_float2((o1.x + ctx[mt][dt][2]) * iv1,
                                                     (o1.y + ctx[mt][dt][3]) * iv1);
            }
        }
    }
}

// ---------------- pre/post kernels ----------------
__global__ void split_bf16_kernel(const float* __restrict__ x,
                                  __nv_bfloat16* __restrict__ hi,
                                  __nv_bfloat16* __restrict__ lo) {
    int i = (blockIdx.x * blockDim.x + threadIdx.x) * 4;
    float4 v = *(const float4*)(x + i);
    __nv_bfloat16 h0 = __float2bfloat16(v.x), h1 = __float2bfloat16(v.y);
    __nv_bfloat16 h2 = __float2bfloat16(v.z), h3 = __float2bfloat16(v.w);
    uint2 hv, lv;
    ((__nv_bfloat162*)&hv)[0] = __halves2bfloat162(h0, h1);
    ((__nv_bfloat162*)&hv)[1] = __halves2bfloat162(h2, h3);
    ((__nv_bfloat162*)&lv)[0] = __floats2bfloat162_rn(v.x - __bfloat162float(h0),
                                                      v.y - __bfloat162float(h1));
    ((__nv_bfloat162*)&lv)[1] = __floats2bfloat162_rn(v.z - __bfloat162float(h2),
                                                      v.w - __bfloat162float(h3));
    *(uint2*)(hi + i) = hv;
    *(uint2*)(lo + i) = lv;
}

__global__ void normalize_attn_kernel(float* __restrict__ attn) {
    // one block per attention row; blockIdx.x = bh*1024 + q
    float iv = g_inv[blockIdx.x];
    float4* row = (float4*)(attn + ((size_t)blockIdx.x << 10));
    float4 v = row[threadIdx.x];
    v.x *= iv; v.y *= iv; v.z *= iv; v.w *= iv;
    row[threadIdx.x] = v;
}

extern "C" void kernel_launch(void* const* d_in, const int* in_sizes, int n_in,
                              void* d_out, int out_size) {
    const float* q    = (const float*)d_in[0];
    const float* k    = (const float*)d_in[1];
    const float* v    = (const float*)d_in[2];
    const int*   mask = (const int*)d_in[3];

    float* out = (float*)d_out;
    const size_t ctx_elems = (size_t)Bn * Hn * Sn * Dn;
    float* ctx_ptr  = out;
    float* attn_ptr = out + ctx_elems;

    __nv_bfloat16 *qh, *ql, *kh, *kl, *vh, *vl;
    cudaGetSymbolAddress((void**)&qh, g_Qh);
    cudaGetSymbolAddress((void**)&ql, g_Ql);
    cudaGetSymbolAddress((void**)&kh, g_Kh);
    cudaGetSymbolAddress((void**)&kl, g_Kl);
    cudaGetSymbolAddress((void**)&vh, g_Vh);
    cudaGetSymbolAddress((void**)&vl, g_Vl);

    const int cvt_blocks = NELEM / (4 * 256);   // 8192
    split_bf16_kernel<<<cvt_blocks, 256>>>(q, qh, ql);
    split_bf16_kernel<<<cvt_blocks, 256>>>(k, kh, kl);
    split_bf16_kernel<<<cvt_blocks, 256>>>(v, vh, vl);

    cudaFuncSetAttribute(sdpa_mma_kernel,
                         cudaFuncAttributeMaxDynamicSharedMemorySize, SM_TOTAL);
    dim3 grid(Sn / TQ, BHn);   // (8, 64)
    sdpa_mma_kernel<<<grid, 256, SM_TOTAL>>>(mask, ctx_ptr, attn_ptr);

    normalize_attn_kernel<<<BHn * Sn, 256>>>(attn_ptr);
}

// round 6
// speedup vs baseline: 2.2784x; 1.0858x over previous
#include <cuda_runtime.h>
#include <cuda_bf16.h>
#include <cstdint>
#include <math.h>

// Problem constants (B=4, H=16, S=1024, D=128, fp32)
#define Bn 4
#define Hn 16
#define Sn 1024
#define Dn 128
#define BHn (Bn*Hn)
#define TQ 64                // q rows per CTA
#define TN 128               // key chunk
#define NCHUNK (Sn/TN)       // 8
#define SCALEF 0.08838834764831845f
#define NELEM (Bn*Hn*Sn*Dn)  // 8388608

// Static split buffers (module-load allocation, allowed)
__device__ __align__(256) __nv_bfloat16 g_Qh[NELEM];
__device__ __align__(256) __nv_bfloat16 g_Ql[NELEM];
__device__ __align__(256) __nv_bfloat16 g_Kh[NELEM];
__device__ __align__(256) __nv_bfloat16 g_Kl[NELEM];
__device__ __align__(256) __nv_bfloat16 g_Vh[NELEM];
__device__ __align__(256) __nv_bfloat16 g_Vl[NELEM];

// ---------------- warp mma helpers ----------------
__device__ __forceinline__ uint32_t smem_u32(const void* p) {
    uint32_t a;
    asm("{ .reg .u64 t; cvta.to.shared.u64 t, %1; cvt.u32.u64 %0, t; }" : "=r"(a) : "l"(p));
    return a;
}
__device__ __forceinline__ void ldsm4(uint32_t r[4], uint32_t addr) {
    asm volatile("ldmatrix.sync.aligned.m8n8.x4.shared.b16 {%0,%1,%2,%3}, [%4];"
        : "=r"(r[0]), "=r"(r[1]), "=r"(r[2]), "=r"(r[3]) : "r"(addr));
}
__device__ __forceinline__ void ldsm4t(uint32_t r[4], uint32_t addr) {
    asm volatile("ldmatrix.sync.aligned.m8n8.x4.trans.shared.b16 {%0,%1,%2,%3}, [%4];"
        : "=r"(r[0]), "=r"(r[1]), "=r"(r[2]), "=r"(r[3]) : "r"(addr));
}
__device__ __forceinline__ void mma16816(float c[4], const uint32_t a[4], uint32_t b0, uint32_t b1) {
    asm volatile(
        "mma.sync.aligned.m16n8k16.row.col.f32.bf16.bf16.f32 "
        "{%0,%1,%2,%3}, {%4,%5,%6,%7}, {%8,%9}, {%0,%1,%2,%3};"
        : "+f"(c[0]), "+f"(c[1]), "+f"(c[2]), "+f"(c[3])
        : "r"(a[0]), "r"(a[1]), "r"(a[2]), "r"(a[3]), "r"(b0), "r"(b1));
}

// Swizzled smem address within a [nrow x 128 bf16] tile (256B rows)
__device__ __forceinline__ uint32_t sw_addr(uint32_t tile, int row, int c16) {
    return tile + (row << 8) + (((c16 ^ (row & 7)) & 15) << 4);
}

// Copy an [NROW x 128] bf16 tile (row stride 128 elems) into swizzled smem. 128 threads.
template<int NROW>
__device__ __forceinline__ void copy_tile(uint32_t dst, const __nv_bfloat16* src, int tid) {
    #pragma unroll
    for (int it = 0; it < NROW / 8; ++it) {
        int idx = tid + 128 * it;
        int row = idx >> 4, c16 = idx & 15;
        uint4 v = *(const uint4*)(src + (size_t)row * 128 + c16 * 8);
        asm volatile("st.shared.v4.b32 [%0], {%1,%2,%3,%4};"
            :: "r"(sw_addr(dst, row, c16)), "r"(v.x), "r"(v.y), "r"(v.z), "r"(v.w));
    }
}

// ---------------- smem ----------------
#define SM_QH 0              // 64 x 256B = 16KB
#define SM_QL 16384
#define SM_KH 32768          // 128 x 256B = 32KB (K chunk, reused for V)
#define SM_KL 65536
#define SM_ROWSUM 98304      // 64 floats
#define SM_INV    98560      // 64 floats
#define SM_TOTAL  98816

extern __shared__ char sm_raw[];

__global__ __launch_bounds__(128)
void sdpa_mma_kernel(const int* __restrict__ Mg,
                     float* __restrict__ ctx_out,
                     float* __restrict__ attn_out)
{
    const int qt = blockIdx.x;               // 0..15
    const int bh = blockIdx.y;               // 0..63
    const int b  = bh >> 4;
    const int tid  = threadIdx.x;
    const int wm   = tid >> 5;               // warp 0..3, owns rows wm*16..wm*16+15
    const int lane = tid & 31;
    const int g  = lane >> 2;                // frag row group
    const int t  = lane & 3;                 // frag col pair
    const int lr = lane & 15, lc = lane >> 4;

    const uint32_t smb = smem_u32(sm_raw);
    float* rowsum_sm = (float*)(sm_raw + SM_ROWSUM);
    float* inv_sm    = (float*)(sm_raw + SM_INV);

    // Q tiles resident
    copy_tile<TQ>(smb + SM_QH, g_Qh + ((size_t)bh * Sn + (size_t)qt * TQ) * Dn, tid);
    copy_tile<TQ>(smb + SM_QL, g_Ql + ((size_t)bh * Sn + (size_t)qt * TQ) * Dn, tid);

    const __nv_bfloat16* Khp = g_Kh + (size_t)bh * Sn * Dn;
    const __nv_bfloat16* Klp = g_Kl + (size_t)bh * Sn * Dn;
    const __nv_bfloat16* Vhp = g_Vh + (size_t)bh * Sn * Dn;
    const __nv_bfloat16* Vlp = g_Vl + (size_t)bh * Sn * Dn;

    const int r0 = qt * TQ + wm * 16 + g;    // global q row (and r0+8)
    const int* mrow0 = Mg + ((size_t)(b * Sn + r0) << 10);
    const int* mrow1 = mrow0 + (8 << 10);
    float* arow0 = attn_out + (((size_t)bh << 10) + r0) * Sn;
    float* arow1 = arow0 + ((size_t)8 * Sn);

    float ctx[16][4];                        // [d n8-tile][frag], rows g/g+8
    #pragma unroll
    for (int j = 0; j < 16; ++j)
        #pragma unroll
        for (int e = 0; e < 4; ++e) ctx[j][e] = 0.0f;
    float rs[2] = {0.f, 0.f};

    for (int ck = 0; ck < NCHUNK; ++ck) {
        __syncthreads();   // V tile of prev chunk fully consumed
        copy_tile<TN>(smb + SM_KH, Khp + (size_t)ck * TN * Dn, tid);
        copy_tile<TN>(smb + SM_KL, Klp + (size_t)ck * TN * Dn, tid);
        __syncthreads();

        // ---- QK^T: warp computes [16 x 128] ----
        float qa[16][4];
        #pragma unroll
        for (int j = 0; j < 16; ++j)
            #pragma unroll
            for (int e = 0; e < 4; ++e) qa[j][e] = 0.0f;

        #pragma unroll
        for (int ks = 0; ks < 8; ++ks) {
            uint32_t aqh[4], aql[4];
            ldsm4(aqh, sw_addr(smb + SM_QH, wm * 16 + lr, ks * 2 + lc));
            ldsm4(aql, sw_addr(smb + SM_QL, wm * 16 + lr, ks * 2 + lc));
            #pragma unroll
            for (int nt16 = 0; nt16 < 8; ++nt16) {
                uint32_t bh4[4], bl4[4];
                ldsm4(bh4, sw_addr(smb + SM_KH, nt16 * 16 + lr, ks * 2 + lc));
                ldsm4(bl4, sw_addr(smb + SM_KL, nt16 * 16 + lr, ks * 2 + lc));
                mma16816(qa[nt16*2],   aqh, bh4[0], bh4[2]);
                mma16816(qa[nt16*2],   aqh, bl4[0], bl4[2]);
                mma16816(qa[nt16*2],   aql, bh4[0], bh4[2]);
                mma16816(qa[nt16*2+1], aqh, bh4[1], bh4[3]);
                mma16816(qa[nt16*2+1], aqh, bl4[1], bl4[3]);
                mma16816(qa[nt16*2+1], aql, bh4[1], bh4[3]);
            }
        }
        __syncthreads();   // K smem reads done -> safe to overwrite with V

        // V copy issues its LDGs now; latency overlaps the epilogue math below
        copy_tile<TN>(smb + SM_KH, Vhp + (size_t)ck * TN * Dn, tid);
        copy_tile<TN>(smb + SM_KL, Vlp + (size_t)ck * TN * Dn, tid);

        // ---- epilogue: scale, mask, exp, rowsum, attn store, pack P frags ----
        uint32_t pah[8][4], pal[8][4];       // [k16-step][a-frag]
        #pragma unroll
        for (int nt = 0; nt < 16; ++nt) {
            int col = ck * TN + nt * 8 + 2 * t;
            int2 m0 = *(const int2*)(mrow0 + col);
            int2 m1 = *(const int2*)(mrow1 + col);
            float p0 = __expf(qa[nt][0] * SCALEF) * (float)(m0.x != 0);
            float p1 = __expf(qa[nt][1] * SCALEF) * (float)(m0.y != 0);
            float p2 = __expf(qa[nt][2] * SCALEF) * (float)(m1.x != 0);
            float p3 = __expf(qa[nt][3] * SCALEF) * (float)(m1.y != 0);
            rs[0] += p0 + p1;
            rs[1] += p2 + p3;
            *(float2*)(arow0 + col) = make_float2(p0, p1);
            *(float2*)(arow1 + col) = make_float2(p2, p3);
            __nv_bfloat16 h0 = __float2bfloat16(p0), h1 = __float2bfloat16(p1);
            __nv_bfloat16 h2 = __float2bfloat16(p2), h3 = __float2bfloat16(p3);
            __nv_bfloat162 hv01 = __halves2bfloat162(h0, h1);
            __nv_bfloat162 hv23 = __halves2bfloat162(h2, h3);
            __nv_bfloat162 lv01 = __floats2bfloat162_rn(p0 - __bfloat162float(h0),
                                                        p1 - __bfloat162float(h1));
            __nv_bfloat162 lv23 = __floats2bfloat162_rn(p2 - __bfloat162float(h2),
                                                        p3 - __bfloat162float(h3));
            int ks = nt >> 1, hf = (nt & 1) * 2;
            pah[ks][hf]     = *(uint32_t*)&hv01;
            pah[ks][hf + 1] = *(uint32_t*)&hv23;
            pal[ks][hf]     = *(uint32_t*)&lv01;
            pal[ks][hf + 1] = *(uint32_t*)&lv23;
        }
        __syncthreads();   // V tiles ready

        // ---- PV: ctx[16 x 128] += P[16 x 128] * V[128 x 128] ----
        #pragma unroll
        for (int ks = 0; ks < 8; ++ks) {
            #pragma unroll
            for (int dt = 0; dt < 8; ++dt) {
                uint32_t vh4[4], vl4[4];
                ldsm4t(vh4, sw_addr(smb + SM_KH, ks * 16 + lr, dt * 2 + lc));
                ldsm4t(vl4, sw_addr(smb + SM_KL, ks * 16 + lr, dt * 2 + lc));
                mma16816(ctx[dt*2],   pah[ks], vh4[0], vh4[1]);
                mma16816(ctx[dt*2],   pah[ks], vl4[0], vl4[1]);
                mma16816(ctx[dt*2],   pal[ks], vh4[0], vh4[1]);
                mma16816(ctx[dt*2+1], pah[ks], vh4[2], vh4[3]);
                mma16816(ctx[dt*2+1], pah[ks], vl4[2], vl4[3]);
                mma16816(ctx[dt*2+1], pal[ks], vh4[2], vh4[3]);
            }
        }
    }

    // ---- rowsum finalize (rows fully warp-owned: shuffles only) ----
    #pragma unroll
    for (int hh = 0; hh < 2; ++hh) {
        rs[hh] += __shfl_xor_sync(0xFFFFFFFFu, rs[hh], 1);
        rs[hh] += __shfl_xor_sync(0xFFFFFFFFu, rs[hh], 2);
    }
    if (t == 0) {
        rowsum_sm[wm * 16 + g]     = rs[0];
        rowsum_sm[wm * 16 + g + 8] = rs[1];
    }
    __syncthreads();
    if (tid < TQ) inv_sm[tid] = 1.0f / rowsum_sm[tid];
    __syncthreads();

    // ---- ctx write (warp owns full rows, direct store) ----
    {
        float iv0 = inv_sm[wm * 16 + g], iv1 = inv_sm[wm * 16 + g + 8];
        float* crow0 = ctx_out + (((size_t)bh << 10) + r0) * Dn;
        float* crow1 = crow0 + (size_t)8 * Dn;
        #pragma unroll
        for (int dt = 0; dt < 16; ++dt) {
            int dd = dt * 8 + 2 * t;
            *(float2*)(crow0 + dd) = make_float2(ctx[dt][0] * iv0, ctx[dt][1] * iv0);
            *(float2*)(crow1 + dd) = make_float2(ctx[dt][2] * iv1, ctx[dt][3] * iv1);
        }
    }

    // ---- fused attn normalize: rescale this CTA's 64x1024 block ----
    {
        float4* ab = (float4*)(attn_out + (((size_t)bh << 10) + (size_t)qt * TQ) * Sn);
        #pragma unroll 4
        for (int i = 0; i < TQ * (Sn / 4) / 128; ++i) {
            int idx = tid + 128 * i;
            int row = idx >> 8;              // /256 float4 per row
            float iv = inv_sm[row];
            float4 v = ab[idx];
            v.x *= iv; v.y *= iv; v.z *= iv; v.w *= iv;
            ab[idx] = v;
        }
    }
}

// ---------------- pre-kernel: split q,k,v into bf16 hi/lo (one launch) ----------------
__global__ void split3_bf16_kernel(const float* __restrict__ q,
                                   const float* __restrict__ k,
                                   const float* __restrict__ v) {
    const float* src;
    __nv_bfloat16 *hi, *lo;
    switch (blockIdx.y) {
        case 0:  src = q; hi = g_Qh; lo = g_Ql; break;
        case 1:  src = k; hi = g_Kh; lo = g_Kl; break;
        default: src = v; hi = g_Vh; lo = g_Vl; break;
    }
    int i = (blockIdx.x * blockDim.x + threadIdx.x) * 4;
    float4 x = *(const float4*)(src + i);
    __nv_bfloat16 h0 = __float2bfloat16(x.x), h1 = __float2bfloat16(x.y);
    __nv_bfloat16 h2 = __float2bfloat16(x.z), h3 = __float2bfloat16(x.w);
    uint2 hv, lv;
    ((__nv_bfloat162*)&hv)[0] = __halves2bfloat162(h0, h1);
    ((__nv_bfloat162*)&hv)[1] = __halves2bfloat162(h2, h3);
    ((__nv_bfloat162*)&lv)[0] = __floats2bfloat162_rn(x.x - __bfloat162float(h0),
                                                      x.y - __bfloat162float(h1));
    ((__nv_bfloat162*)&lv)[1] = __floats2bfloat162_rn(x.z - __bfloat162float(h2),
                                                      x.w - __bfloat162float(h3));
    *(uint2*)(hi + i) = hv;
    *(uint2*)(lo + i) = lv;
}

extern "C" void kernel_launch(void* const* d_in, const int* in_sizes, int n_in,
                              void* d_out, int out_size) {
    const float* q    = (const float*)d_in[0];
    const float* k    = (const float*)d_in[1];
    const float* v    = (const float*)d_in[2];
    const int*   mask = (const int*)d_in[3];

    float* out = (float*)d_out;
    const size_t ctx_elems = (size_t)Bn * Hn * Sn * Dn;
    float* ctx_ptr  = out;
    float* attn_ptr = out + ctx_elems;

    split3_bf16_kernel<<<dim3(NELEM / (4 * 256), 3), 256>>>(q, k, v);

    cudaFuncSetAttribute(sdpa_mma_kernel,
                         cudaFuncAttributeMaxDynamicSharedMemorySize, SM_TOTAL);
    dim3 grid(Sn / TQ, BHn);   // (16, 64)
    sdpa_mma_kernel<<<grid, 128, SM_TOTAL>>>(mask, ctx_ptr, attn_ptr);
}

// round 16
// speedup vs baseline: 2.3773x; 1.0434x over previous
#include <cuda_runtime.h>
#include <cuda_bf16.h>
#include <cstdint>
#include <math.h>

// Problem constants (B=4, H=16, S=1024, D=128, fp32)
#define Bn 4
#define Hn 16
#define Sn 1024
#define Dn 128
#define BHn (Bn*Hn)
#define TQ 64                // q rows per CTA
#define TN 64                // key chunk
#define NCHUNK (Sn/TN)       // 16
#define SCALEF 0.08838834764831845f
#define NELEM (Bn*Hn*Sn*Dn)  // 8388608

// Static split buffers (module-load allocation, allowed)
__device__ __align__(256) __nv_bfloat16 g_Qh[NELEM];
__device__ __align__(256) __nv_bfloat16 g_Ql[NELEM];
__device__ __align__(256) __nv_bfloat16 g_Kh[NELEM];
__device__ __align__(256) __nv_bfloat16 g_Kl[NELEM];
__device__ __align__(256) __nv_bfloat16 g_Vh[NELEM];
__device__ __align__(256) __nv_bfloat16 g_Vl[NELEM];

// ---------------- warp mma helpers ----------------
__device__ __forceinline__ uint32_t smem_u32(const void* p) {
    uint32_t a;
    asm("{ .reg .u64 t; cvta.to.shared.u64 t, %1; cvt.u32.u64 %0, t; }" : "=r"(a) : "l"(p));
    return a;
}
__device__ __forceinline__ void ldsm4(uint32_t r[4], uint32_t addr) {
    asm volatile("ldmatrix.sync.aligned.m8n8.x4.shared.b16 {%0,%1,%2,%3}, [%4];"
        : "=r"(r[0]), "=r"(r[1]), "=r"(r[2]), "=r"(r[3]) : "r"(addr));
}
__device__ __forceinline__ void ldsm4t(uint32_t r[4], uint32_t addr) {
    asm volatile("ldmatrix.sync.aligned.m8n8.x4.trans.shared.b16 {%0,%1,%2,%3}, [%4];"
        : "=r"(r[0]), "=r"(r[1]), "=r"(r[2]), "=r"(r[3]) : "r"(addr));
}
__device__ __forceinline__ void mma16816(float c[4], const uint32_t a[4], uint32_t b0, uint32_t b1) {
    asm volatile(
        "mma.sync.aligned.m16n8k16.row.col.f32.bf16.bf16.f32 "
        "{%0,%1,%2,%3}, {%4,%5,%6,%7}, {%8,%9}, {%0,%1,%2,%3};"
        : "+f"(c[0]), "+f"(c[1]), "+f"(c[2]), "+f"(c[3])
        : "r"(a[0]), "r"(a[1]), "r"(a[2]), "r"(a[3]), "r"(b0), "r"(b1));
}

// Swizzled smem address in a [nrow x 128 bf16] tile (256B rows)
__device__ __forceinline__ uint32_t sw_addr(uint32_t tile, int row, int c16) {
    return tile + (row << 8) + (((c16 ^ (row & 7)) & 15) << 4);
}
// Swizzled smem address in a [nrow x 64 bf16] tile (128B rows) — for P
__device__ __forceinline__ uint32_t sw_addr64(uint32_t tile, int row, int c16) {
    return tile + (row << 7) + (((c16 ^ (row & 7)) & 7) << 4);
}

// Copy an [NROW x 128] bf16 tile (row stride 128 elems) into swizzled smem. 128 threads.
template<int NROW>
__device__ __forceinline__ void copy_tile(uint32_t dst, const __nv_bfloat16* src, int tid) {
    #pragma unroll
    for (int it = 0; it < NROW / 8; ++it) {
        int idx = tid + 128 * it;
        int row = idx >> 4, c16 = idx & 15;
        uint4 v = *(const uint4*)(src + (size_t)row * 128 + c16 * 8);
        asm volatile("st.shared.v4.b32 [%0], {%1,%2,%3,%4};"
            :: "r"(sw_addr(dst, row, c16)), "r"(v.x), "r"(v.y), "r"(v.z), "r"(v.w));
    }
}

// ---------------- smem (80.5 KB -> 2 CTAs/SM) ----------------
#define SM_QH 0              // 64 x 256B = 16KB
#define SM_QL 16384
#define SM_KH 32768          // 64 x 256B = 16KB (K chunk, reused for V)
#define SM_KL 49152
#define SM_PH 65536          // 64 x 128B = 8KB
#define SM_PL 73728
#define SM_ROWSUM 81920      // 64 floats
#define SM_INV    82176      // 64 floats
#define SM_TOTAL  82432

extern __shared__ char sm_raw[];

__global__ __launch_bounds__(128)
void sdpa_mma_kernel(const int* __restrict__ Mg,
                     float* __restrict__ ctx_out,
                     float* __restrict__ attn_out)
{
    const int qt = blockIdx.x;               // 0..15
    const int bh = blockIdx.y;               // 0..63
    const int b  = bh >> 4;
    const int tid  = threadIdx.x;
    const int wm   = tid >> 5;               // warp 0..3 owns q rows wm*16..+15
    const int lane = tid & 31;
    const int g  = lane >> 2;
    const int t  = lane & 3;
    const int lr = lane & 15, lc = lane >> 4;

    const uint32_t smb = smem_u32(sm_raw);
    float* rowsum_sm = (float*)(sm_raw + SM_ROWSUM);
    float* inv_sm    = (float*)(sm_raw + SM_INV);

    // Q tiles resident
    copy_tile<TQ>(smb + SM_QH, g_Qh + ((size_t)bh * Sn + (size_t)qt * TQ) * Dn, tid);
    copy_tile<TQ>(smb + SM_QL, g_Ql + ((size_t)bh * Sn + (size_t)qt * TQ) * Dn, tid);

    const __nv_bfloat16* Khp = g_Kh + (size_t)bh * Sn * Dn;
    const __nv_bfloat16* Klp = g_Kl + (size_t)bh * Sn * Dn;
    const __nv_bfloat16* Vhp = g_Vh + (size_t)bh * Sn * Dn;
    const __nv_bfloat16* Vlp = g_Vl + (size_t)bh * Sn * Dn;

    const int r0 = qt * TQ + wm * 16 + g;    // global q row (and r0+8)
    const int* mrow0 = Mg + ((size_t)(b * Sn + r0) << 10);
    const int* mrow1 = mrow0 + (8 << 10);
    float* arow0 = attn_out + (((size_t)bh << 10) + r0) * Sn;
    float* arow1 = arow0 + ((size_t)8 * Sn);

    float ctx[16][4];
    #pragma unroll
    for (int j = 0; j < 16; ++j)
        #pragma unroll
        for (int e = 0; e < 4; ++e) ctx[j][e] = 0.0f;
    float rs[2] = {0.f, 0.f};

    for (int ck = 0; ck < NCHUNK; ++ck) {
        __syncthreads();   // prev chunk's PV reads of V/P done
        copy_tile<TN>(smb + SM_KH, Khp + (size_t)ck * TN * Dn, tid);
        copy_tile<TN>(smb + SM_KL, Klp + (size_t)ck * TN * Dn, tid);
        __syncthreads();

        // ---- QK^T: warp computes [16 x 64] ----
        float qa[8][4];
        #pragma unroll
        for (int j = 0; j < 8; ++j)
            #pragma unroll
            for (int e = 0; e < 4; ++e) qa[j][e] = 0.0f;

        #pragma unroll
        for (int ks = 0; ks < 8; ++ks) {
            uint32_t aqh[4], aql[4];
            ldsm4(aqh, sw_addr(smb + SM_QH, wm * 16 + lr, ks * 2 + lc));
            ldsm4(aql, sw_addr(smb + SM_QL, wm * 16 + lr, ks * 2 + lc));
            #pragma unroll
            for (int nt16 = 0; nt16 < 4; ++nt16) {
                uint32_t bh4[4], bl4[4];
                ldsm4(bh4, sw_addr(smb + SM_KH, nt16 * 16 + lr, ks * 2 + lc));
                ldsm4(bl4, sw_addr(smb + SM_KL, nt16 * 16 + lr, ks * 2 + lc));
                mma16816(qa[nt16*2],   aqh, bh4[0], bh4[2]);
                mma16816(qa[nt16*2],   aqh, bl4[0], bl4[2]);
                mma16816(qa[nt16*2],   aql, bh4[0], bh4[2]);
                mma16816(qa[nt16*2+1], aqh, bh4[1], bh4[3]);
                mma16816(qa[nt16*2+1], aqh, bl4[1], bl4[3]);
                mma16816(qa[nt16*2+1], aql, bh4[1], bh4[3]);
            }
        }
        __syncthreads();   // K smem reads done -> safe to overwrite with V

        // V copy issues LDGs now; latency overlaps epilogue math below
        copy_tile<TN>(smb + SM_KH, Vhp + (size_t)ck * TN * Dn, tid);
        copy_tile<TN>(smb + SM_KL, Vlp + (size_t)ck * TN * Dn, tid);

        // ---- epilogue: scale, mask, exp, rowsum, attn store, P -> smem ----
        #pragma unroll
        for (int nt = 0; nt < 8; ++nt) {
            int col = ck * TN + nt * 8 + 2 * t;
            int2 m0 = *(const int2*)(mrow0 + col);
            int2 m1 = *(const int2*)(mrow1 + col);
            float p0 = __expf(qa[nt][0] * SCALEF) * (float)(m0.x != 0);
            float p1 = __expf(qa[nt][1] * SCALEF) * (float)(m0.y != 0);
            float p2 = __expf(qa[nt][2] * SCALEF) * (float)(m1.x != 0);
            float p3 = __expf(qa[nt][3] * SCALEF) * (float)(m1.y != 0);
            rs[0] += p0 + p1;
            rs[1] += p2 + p3;
            *(float2*)(arow0 + col) = make_float2(p0, p1);
            *(float2*)(arow1 + col) = make_float2(p2, p3);
            __nv_bfloat16 h0 = __float2bfloat16(p0), h1 = __float2bfloat16(p1);
            __nv_bfloat16 h2 = __float2bfloat16(p2), h3 = __float2bfloat16(p3);
            __nv_bfloat162 hv01 = __halves2bfloat162(h0, h1);
            __nv_bfloat162 hv23 = __halves2bfloat162(h2, h3);
            __nv_bfloat162 lv01 = __floats2bfloat162_rn(p0 - __bfloat162float(h0),
                                                        p1 - __bfloat162float(h1));
            __nv_bfloat162 lv23 = __floats2bfloat162_rn(p2 - __bfloat162float(h2),
                                                        p3 - __bfloat162float(h3));
            // P[row][cols nt*8+2t..+1], 4B stores, conflict-free under sw_addr64
            uint32_t a0 = sw_addr64(smb + SM_PH, wm * 16 + g,     nt) + 4 * t;
            uint32_t a1 = sw_addr64(smb + SM_PH, wm * 16 + g + 8, nt) + 4 * t;
            asm volatile("st.shared.b32 [%0], %1;" :: "r"(a0), "r"(*(uint32_t*)&hv01));
            asm volatile("st.shared.b32 [%0], %1;" :: "r"(a1), "r"(*(uint32_t*)&hv23));
            uint32_t a2 = sw_addr64(smb + SM_PL, wm * 16 + g,     nt) + 4 * t;
            uint32_t a3 = sw_addr64(smb + SM_PL, wm * 16 + g + 8, nt) + 4 * t;
            asm volatile("st.shared.b32 [%0], %1;" :: "r"(a2), "r"(*(uint32_t*)&lv01));
            asm volatile("st.shared.b32 [%0], %1;" :: "r"(a3), "r"(*(uint32_t*)&lv23));
        }
        __syncthreads();   // V tiles + P tiles ready

        // ---- PV: ctx[16 x 128] += P[16 x 64] * V[64 x 128] ----
        #pragma unroll
        for (int ks = 0; ks < 4; ++ks) {
            uint32_t pah[4], pal[4];
            ldsm4(pah, sw_addr64(smb + SM_PH, wm * 16 + lr, ks * 2 + lc));
            ldsm4(pal, sw_addr64(smb + SM_PL, wm * 16 + lr, ks * 2 + lc));
            #pragma unroll
            for (int dt = 0; dt < 8; ++dt) {
                uint32_t vh4[4], vl4[4];
                ldsm4t(vh4, sw_addr(smb + SM_KH, ks * 16 + lr, dt * 2 + lc));
                ldsm4t(vl4, sw_addr(smb + SM_KL, ks * 16 + lr, dt * 2 + lc));
                mma16816(ctx[dt*2],   pah, vh4[0], vh4[1]);
                mma16816(ctx[dt*2],   pah, vl4[0], vl4[1]);
                mma16816(ctx[dt*2],   pal, vh4[0], vh4[1]);
                mma16816(ctx[dt*2+1], pah, vh4[2], vh4[3]);
                mma16816(ctx[dt*2+1], pah, vl4[2], vl4[3]);
                mma16816(ctx[dt*2+1], pal, vh4[2], vh4[3]);
            }
        }
    }

    // ---- rowsum finalize (warp-local) ----
    #pragma unroll
    for (int hh = 0; hh < 2; ++hh) {
        rs[hh] += __shfl_xor_sync(0xFFFFFFFFu, rs[hh], 1);
        rs[hh] += __shfl_xor_sync(0xFFFFFFFFu, rs[hh], 2);
    }
    if (t == 0) {
        rowsum_sm[wm * 16 + g]     = rs[0];
        rowsum_sm[wm * 16 + g + 8] = rs[1];
    }
    __syncthreads();
    if (tid < TQ) inv_sm[tid] = 1.0f / rowsum_sm[tid];
    __syncthreads();

    // ---- ctx write ----
    {
        float iv0 = inv_sm[wm * 16 + g], iv1 = inv_sm[wm * 16 + g + 8];
        float* crow0 = ctx_out + (((size_t)bh << 10) + r0) * Dn;
        float* crow1 = crow0 + (size_t)8 * Dn;
        #pragma unroll
        for (int dt = 0; dt < 16; ++dt) {
            int dd = dt * 8 + 2 * t;
            *(float2*)(crow0 + dd) = make_float2(ctx[dt][0] * iv0, ctx[dt][1] * iv0);
            *(float2*)(crow1 + dd) = make_float2(ctx[dt][2] * iv1, ctx[dt][3] * iv1);
        }
    }

    // ---- fused attn normalize: rescale this CTA's 64x1024 block ----
    {
        float4* ab = (float4*)(attn_out + (((size_t)bh << 10) + (size_t)qt * TQ) * Sn);
        #pragma unroll 4
        for (int i = 0; i < TQ * (Sn / 4) / 128; ++i) {
            int idx = tid + 128 * i;
            int row = idx >> 8;              // 256 float4 per row
            float iv = inv_sm[row];
            float4 v = ab[idx];
            v.x *= iv; v.y *= iv; v.z *= iv; v.w *= iv;
            ab[idx] = v;
        }
    }
}

// ---------------- pre-kernel: split q,k,v into bf16 hi/lo (one launch) ----------------
__global__ void split3_bf16_kernel(const float* __restrict__ q,
                                   const float* __restrict__ k,
                                   const float* __restrict__ v) {
    const float* src;
    __nv_bfloat16 *hi, *lo;
    switch (blockIdx.y) {
        case 0:  src = q; hi = g_Qh; lo = g_Ql; break;
        case 1:  src = k; hi = g_Kh; lo = g_Kl; break;
        default: src = v; hi = g_Vh; lo = g_Vl; break;
    }
    int i = (blockIdx.x * blockDim.x + threadIdx.x) * 4;
    float4 x = *(const float4*)(src + i);
    __nv_bfloat16 h0 = __float2bfloat16(x.x), h1 = __float2bfloat16(x.y);
    __nv_bfloat16 h2 = __float2bfloat16(x.z), h3 = __float2bfloat16(x.w);
    uint2 hv, lv;
    ((__nv_bfloat162*)&hv)[0] = __halves2bfloat162(h0, h1);
    ((__nv_bfloat162*)&hv)[1] = __halves2bfloat162(h2, h3);
    ((__nv_bfloat162*)&lv)[0] = __floats2bfloat162_rn(x.x - __bfloat162float(h0),
                                                      x.y - __bfloat162float(h1));
    ((__nv_bfloat162*)&lv)[1] = __floats2bfloat162_rn(x.z - __bfloat162float(h2),
                                                      x.w - __bfloat162float(h3));
    *(uint2*)(hi + i) = hv;
    *(uint2*)(lo + i) = lv;
}

extern "C" void kernel_launch(void* const* d_in, const int* in_sizes, int n_in,
                              void* d_out, int out_size) {
    const float* q    = (const float*)d_in[0];
    const float* k    = (const float*)d_in[1];
    const float* v    = (const float*)d_in[2];
    const int*   mask = (const int*)d_in[3];

    float* out = (float*)d_out;
    const size_t ctx_elems = (size_t)Bn * Hn * Sn * Dn;
    float* ctx_ptr  = out;
    float* attn_ptr = out + ctx_elems;

    split3_bf16_kernel<<<dim3(NELEM / (4 * 256), 3), 256>>>(q, k, v);

    cudaFuncSetAttribute(sdpa_mma_kernel,
                         cudaFuncAttributeMaxDynamicSharedMemorySize, SM_TOTAL);
    dim3 grid(Sn / TQ, BHn);   // (16, 64)
    sdpa_mma_kernel<<<grid, 128, SM_TOTAL>>>(mask, ctx_ptr, attn_ptr);
}